// round 6
// baseline (speedup 1.0000x reference)
#include <cuda_runtime.h>

#define Tn 512
#define Bn 256
#define Hn 32

// Scratch (no cudaMalloc allowed): device globals.
__device__ float g_h0[(size_t)Bn * Tn * 64];          // [B][T][64]  layer-0 output (fwd|bwd)
__device__ float g_gx1[(size_t)2 * Tn * Bn * 128];    // [dir][t][B][128] layer-1 input projection
__device__ float g_hn[Bn * 64];                       // [B][64] final hidden (l1 fwd|bwd)

__device__ __forceinline__ float sigf(float x) {
    // 1/(1+e^-x); __expf(-x)->inf for very negative x gives 0, correct limit.
    return __fdividef(1.0f, 1.0f + __expf(-x));
}
__device__ __forceinline__ float tanh_f(float x) {
    // overflow-safe: e = exp(-2|x|) in (0,1]
    float ax = fabsf(x);
    float e = __expf(-2.0f * ax);
    float t = __fdividef(1.0f - e, 1.0f + e);
    return copysignf(t, x);
}

// ---------------------------------------------------------------------------
// Layer-0 bidirectional LSTM. One warp = one batch row (one direction).
// grid: (B/4, 2 dirs), block: 128 (4 warps). Weights in registers, h broadcast
// via shuffle. Writes g_h0[b][t][dir*32 + j].
// ---------------------------------------------------------------------------
__global__ void __launch_bounds__(128, 1) lstm_layer0(
    const float* __restrict__ x,
    const float* __restrict__ wih_f, const float* __restrict__ whh_f,
    const float* __restrict__ bih_f, const float* __restrict__ bhh_f,
    const float* __restrict__ wih_b, const float* __restrict__ whh_b,
    const float* __restrict__ bih_b, const float* __restrict__ bhh_b)
{
    const int dir  = blockIdx.y;
    const int warp = threadIdx.x >> 5;
    const int j    = threadIdx.x & 31;
    const int b    = blockIdx.x * 4 + warp;

    const float* wih = dir ? wih_b : wih_f;
    const float* whh = dir ? whh_b : whh_f;
    const float* bih = dir ? bih_b : bih_f;
    const float* bhh = dir ? bhh_b : bhh_f;

    // Per-thread weights: rows j, 32+j, 64+j, 96+j of w_hh (gate order i,f,g,o)
    float wh[4][32];
    float wi[4][3];
    float bias[4];
#pragma unroll
    for (int q = 0; q < 4; q++) {
        const int row = q * 32 + j;
        const float4* src = reinterpret_cast<const float4*>(whh + row * 32);
#pragma unroll
        for (int v = 0; v < 8; v++) {
            float4 f = src[v];
            wh[q][4*v+0] = f.x; wh[q][4*v+1] = f.y;
            wh[q][4*v+2] = f.z; wh[q][4*v+3] = f.w;
        }
        wi[q][0] = wih[row*3+0];
        wi[q][1] = wih[row*3+1];
        wi[q][2] = wih[row*3+2];
        bias[q]  = bih[row] + bhh[row];
    }

    float h = 0.0f, c = 0.0f;
    const float* xb = x + (size_t)b * Tn * 3;
    float* ob = g_h0 + (size_t)b * Tn * 64 + dir * 32 + j;

    for (int t = 0; t < Tn; t++) {
        const int te = dir ? (Tn - 1 - t) : t;
        const float x0 = __ldg(xb + te*3 + 0);
        const float x1 = __ldg(xb + te*3 + 1);
        const float x2 = __ldg(xb + te*3 + 2);

        float acc[4];
#pragma unroll
        for (int q = 0; q < 4; q++)
            acc[q] = bias[q] + wi[q][0]*x0 + wi[q][1]*x1 + wi[q][2]*x2;

#pragma unroll
        for (int k = 0; k < 32; k++) {
            const float hk = __shfl_sync(0xffffffffu, h, k);
#pragma unroll
            for (int q = 0; q < 4; q++) acc[q] += wh[q][k] * hk;
        }

        const float ig = sigf(acc[0]);
        const float fg = sigf(acc[1]);
        const float gg = tanh_f(acc[2]);
        const float og = sigf(acc[3]);
        c = fg * c + ig * gg;
        h = og * tanh_f(c);

        ob[(size_t)te * 64] = h;
    }
}

// ---------------------------------------------------------------------------
// Layer-1 input projection: gx1[dir][t][b][g] = sum_k h0[b][t][k]*w_ih1[g][k] + bias[g]
// grid: (T, B/32, 2), block 256. FFMA2 (packed f32x2) over batch pairs.
// ---------------------------------------------------------------------------
__global__ void __launch_bounds__(256) gx1_gemm(
    const float* __restrict__ wih1_f, const float* __restrict__ bih1_f, const float* __restrict__ bhh1_f,
    const float* __restrict__ wih1_b, const float* __restrict__ bih1_b, const float* __restrict__ bhh1_b)
{
    const int t   = blockIdx.x;
    const int b0  = blockIdx.y * 32;
    const int dir = blockIdx.z;
    const float* w  = dir ? wih1_b : wih1_f;
    const float* bi = dir ? bih1_b : bih1_f;
    const float* bh = dir ? bhh1_b : bhh1_f;

    __shared__ float w_s[128 * 65];    // padded stride 65: conflict-free row reads
    __shared__ float h_s[64 * 34];     // transposed [k][b], even pad keeps 8B align
    __shared__ float bias_s[128];

    const int tid = threadIdx.x;
    for (int i = tid; i < 128 * 64; i += 256) {
        const int g = i >> 6, k = i & 63;
        w_s[g * 65 + k] = w[i];
    }
    for (int i = tid; i < 32 * 64; i += 256) {
        const int bl = i >> 6, k = i & 63;
        h_s[k * 34 + bl] = g_h0[((size_t)(b0 + bl) * Tn + t) * 64 + k];
    }
    if (tid < 128) bias_s[tid] = bi[tid] + bh[tid];
    __syncthreads();

    const int g     = tid & 127;
    const int half  = tid >> 7;        // which 16 batch rows (0 or 1)
    const int bbase = half * 16;

    unsigned long long acc[8];
    {
        const float bg = bias_s[g];
        unsigned long long bias2;
        asm("mov.b64 %0, {%1,%1};" : "=l"(bias2) : "f"(bg));
#pragma unroll
        for (int p = 0; p < 8; p++) acc[p] = bias2;
    }

#pragma unroll 8
    for (int k = 0; k < 64; k++) {
        const float wv = w_s[g * 65 + k];
        unsigned long long w2;
        asm("mov.b64 %0, {%1,%1};" : "=l"(w2) : "f"(wv));
        const unsigned long long* hrow =
            reinterpret_cast<const unsigned long long*>(&h_s[k * 34 + bbase]);
#pragma unroll
        for (int p = 0; p < 8; p++) {
            asm("fma.rn.f32x2 %0, %1, %2, %0;" : "+l"(acc[p]) : "l"(w2), "l"(hrow[p]));
        }
    }

    float* out = g_gx1 + (((size_t)dir * Tn + t) * Bn + b0 + bbase) * 128 + g;
#pragma unroll
    for (int p = 0; p < 8; p++) {
        float lo, hi;
        asm("mov.b64 {%0,%1}, %2;" : "=f"(lo), "=f"(hi) : "l"(acc[p]));
        out[(size_t)(2 * p) * 128]     = lo;
        out[(size_t)(2 * p + 1) * 128] = hi;
    }
}

// ---------------------------------------------------------------------------
// Layer-1 bidirectional LSTM. Same structure as layer0, but the input
// contribution is the precomputed gx1 (prefetched 2 steps ahead). Only the
// final hidden state is stored.
// ---------------------------------------------------------------------------
__global__ void __launch_bounds__(128, 1) lstm_layer1(
    const float* __restrict__ whh_f, const float* __restrict__ whh_b)
{
    const int dir  = blockIdx.y;
    const int warp = threadIdx.x >> 5;
    const int j    = threadIdx.x & 31;
    const int b    = blockIdx.x * 4 + warp;
    const float* whh = dir ? whh_b : whh_f;

    float wh[4][32];
#pragma unroll
    for (int q = 0; q < 4; q++) {
        const float4* src = reinterpret_cast<const float4*>(whh + (q * 32 + j) * 32);
#pragma unroll
        for (int v = 0; v < 8; v++) {
            float4 f = src[v];
            wh[q][4*v+0] = f.x; wh[q][4*v+1] = f.y;
            wh[q][4*v+2] = f.z; wh[q][4*v+3] = f.w;
        }
    }

    const float* gxd = g_gx1 + (size_t)dir * Tn * Bn * 128 + (size_t)b * 128 + j;

    // depth-2 prefetch ring
    float pf[2][4];
#pragma unroll
    for (int s = 0; s < 2; s++) {
        const int te = dir ? (Tn - 1 - s) : s;
        const float* p = gxd + (size_t)te * Bn * 128;
#pragma unroll
        for (int q = 0; q < 4; q++) pf[s][q] = __ldg(p + q * 32);
    }

    float h = 0.0f, c = 0.0f;
    for (int t = 0; t < Tn; t++) {
        float acc[4];
#pragma unroll
        for (int q = 0; q < 4; q++) acc[q] = pf[t & 1][q];

        const int tn = t + 2;
        if (tn < Tn) {
            const int te = dir ? (Tn - 1 - tn) : tn;
            const float* p = gxd + (size_t)te * Bn * 128;
#pragma unroll
            for (int q = 0; q < 4; q++) pf[t & 1][q] = __ldg(p + q * 32);
        }

#pragma unroll
        for (int k = 0; k < 32; k++) {
            const float hk = __shfl_sync(0xffffffffu, h, k);
#pragma unroll
            for (int q = 0; q < 4; q++) acc[q] += wh[q][k] * hk;
        }

        const float ig = sigf(acc[0]);
        const float fg = sigf(acc[1]);
        const float gg = tanh_f(acc[2]);
        const float og = sigf(acc[3]);
        c = fg * c + ig * gg;
        h = og * tanh_f(c);
    }

    g_hn[b * 64 + dir * 32 + j] = h;
}

// ---------------------------------------------------------------------------
// Classifier head: out = relu(hn @ wc1^T + bc1) @ wc2^T + bc2
// grid: B/128 blocks, one thread per batch row.
// ---------------------------------------------------------------------------
__global__ void __launch_bounds__(128) classifier(
    const float* __restrict__ wc1, const float* __restrict__ bc1,
    const float* __restrict__ wc2, const float* __restrict__ bc2,
    float* __restrict__ out)
{
    __shared__ float w1[32 * 64];
    __shared__ float b1[32];
    __shared__ float w2[2 * 32];
    __shared__ float b2[2];

    const int tid = threadIdx.x;
    for (int i = tid; i < 32 * 64; i += 128) w1[i] = wc1[i];
    if (tid < 32) b1[tid] = bc1[tid];
    if (tid < 64) w2[tid] = wc2[tid];
    if (tid < 2)  b2[tid] = bc2[tid];
    __syncthreads();

    const int b = blockIdx.x * 128 + tid;
    float hx[64];
#pragma unroll
    for (int k = 0; k < 64; k++) hx[k] = g_hn[b * 64 + k];

    float o0 = b2[0], o1 = b2[1];
#pragma unroll 4
    for (int m = 0; m < 32; m++) {
        float a = b1[m];
#pragma unroll
        for (int k = 0; k < 64; k++) a += w1[m * 64 + k] * hx[k];
        a = fmaxf(a, 0.0f);
        o0 += w2[m] * a;
        o1 += w2[32 + m] * a;
    }
    out[b * 2 + 0] = o0;
    out[b * 2 + 1] = o1;
}

// ---------------------------------------------------------------------------
extern "C" void kernel_launch(void* const* d_in, const int* in_sizes, int n_in,
                              void* d_out, int out_size)
{
    (void)in_sizes; (void)n_in; (void)out_size;
    const float* x     = (const float*)d_in[0];
    const float* wih0f = (const float*)d_in[1];
    const float* whh0f = (const float*)d_in[2];
    const float* bih0f = (const float*)d_in[3];
    const float* bhh0f = (const float*)d_in[4];
    const float* wih0b = (const float*)d_in[5];
    const float* whh0b = (const float*)d_in[6];
    const float* bih0b = (const float*)d_in[7];
    const float* bhh0b = (const float*)d_in[8];
    const float* wih1f = (const float*)d_in[9];
    const float* whh1f = (const float*)d_in[10];
    const float* bih1f = (const float*)d_in[11];
    const float* bhh1f = (const float*)d_in[12];
    const float* wih1b = (const float*)d_in[13];
    const float* whh1b = (const float*)d_in[14];
    const float* bih1b = (const float*)d_in[15];
    const float* bhh1b = (const float*)d_in[16];
    const float* wc1   = (const float*)d_in[17];
    const float* bc1   = (const float*)d_in[18];
    const float* wc2   = (const float*)d_in[19];
    const float* bc2   = (const float*)d_in[20];

    lstm_layer0<<<dim3(Bn / 4, 2), 128>>>(x, wih0f, whh0f, bih0f, bhh0f,
                                          wih0b, whh0b, bih0b, bhh0b);
    gx1_gemm<<<dim3(Tn, Bn / 32, 2), 256>>>(wih1f, bih1f, bhh1f,
                                            wih1b, bih1b, bhh1b);
    lstm_layer1<<<dim3(Bn / 4, 2), 128>>>(whh1f, whh1b);
    classifier<<<dim3(Bn / 128), 128>>>(wc1, bc1, wc2, bc2, (float*)d_out);
}

// round 7
// speedup vs baseline: 1.1096x; 1.1096x over previous
#include <cuda_runtime.h>

#define Tn 512
#define Bn 256
#define Hn 32

// Scratch (no cudaMalloc allowed): device globals.
__device__ float g_h0[(size_t)Bn * Tn * 64];          // [B][T][64]  layer-0 output (fwd|bwd)
__device__ float g_gx1[(size_t)2 * Tn * Bn * 128];    // [dir][t][B][128] layer-1 input projection

// ---- packed f32x2 helpers (Blackwell FFMA2 path, PTX-only) ----
__device__ __forceinline__ unsigned long long pack2(float a, float b) {
    unsigned long long r; asm("mov.b64 %0,{%1,%2};" : "=l"(r) : "f"(a), "f"(b)); return r;
}
__device__ __forceinline__ unsigned long long dup2(float a) {
    unsigned long long r; asm("mov.b64 %0,{%1,%1};" : "=l"(r) : "f"(a)); return r;
}
__device__ __forceinline__ void unpack2(unsigned long long v, float& lo, float& hi) {
    asm("mov.b64 {%0,%1},%2;" : "=f"(lo), "=f"(hi) : "l"(v));
}
__device__ __forceinline__ void ffma2(unsigned long long& acc, unsigned long long a,
                                      unsigned long long b) {
    asm("fma.rn.f32x2 %0,%1,%2,%0;" : "+l"(acc) : "l"(a), "l"(b));
}

__device__ __forceinline__ float sigf(float x) {
    return __fdividef(1.0f, 1.0f + __expf(-x));
}
__device__ __forceinline__ float tanh_f(float x) {
    float ax = fabsf(x);
    float e = __expf(-2.0f * ax);
    float t = __fdividef(1.0f - e, 1.0f + e);
    return copysignf(t, x);
}

// ---------------------------------------------------------------------------
// Layer-0 bidirectional LSTM. One warp = one (batch row, direction).
// Gate-paired FFMA2: accP=(i,f), accQ=(g,o). x prefetched 2 steps ahead.
// ---------------------------------------------------------------------------
__global__ void __launch_bounds__(128, 1) lstm_layer0(
    const float* __restrict__ x,
    const float* __restrict__ wih_f, const float* __restrict__ whh_f,
    const float* __restrict__ bih_f, const float* __restrict__ bhh_f,
    const float* __restrict__ wih_b, const float* __restrict__ whh_b,
    const float* __restrict__ bih_b, const float* __restrict__ bhh_b)
{
    const int dir  = blockIdx.y;
    const int warp = threadIdx.x >> 5;
    const int j    = threadIdx.x & 31;
    const int b    = blockIdx.x * 4 + warp;

    const float* wih = dir ? wih_b : wih_f;
    const float* whh = dir ? whh_b : whh_f;
    const float* bih = dir ? bih_b : bih_f;
    const float* bhh = dir ? bhh_b : bhh_f;

    // Packed recurrent weights: whP[k]=(w_i[j][k], w_f[j][k]); whQ[k]=(w_g, w_o)
    unsigned long long whP[32], whQ[32];
    {
        const float4* rI = reinterpret_cast<const float4*>(whh + (0   + j) * 32);
        const float4* rF = reinterpret_cast<const float4*>(whh + (32  + j) * 32);
        const float4* rG = reinterpret_cast<const float4*>(whh + (64  + j) * 32);
        const float4* rO = reinterpret_cast<const float4*>(whh + (96  + j) * 32);
#pragma unroll
        for (int v = 0; v < 8; v++) {
            float4 a = rI[v], c = rF[v];
            whP[4*v+0] = pack2(a.x, c.x); whP[4*v+1] = pack2(a.y, c.y);
            whP[4*v+2] = pack2(a.z, c.z); whP[4*v+3] = pack2(a.w, c.w);
        }
#pragma unroll
        for (int v = 0; v < 8; v++) {
            float4 a = rG[v], c = rO[v];
            whQ[4*v+0] = pack2(a.x, c.x); whQ[4*v+1] = pack2(a.y, c.y);
            whQ[4*v+2] = pack2(a.z, c.z); whQ[4*v+3] = pack2(a.w, c.w);
        }
    }
    unsigned long long wiP[3], wiQ[3], biasP, biasQ;
#pragma unroll
    for (int kk = 0; kk < 3; kk++) {
        wiP[kk] = pack2(wih[(0  + j)*3 + kk], wih[(32 + j)*3 + kk]);
        wiQ[kk] = pack2(wih[(64 + j)*3 + kk], wih[(96 + j)*3 + kk]);
    }
    biasP = pack2(bih[j]      + bhh[j],      bih[32 + j] + bhh[32 + j]);
    biasQ = pack2(bih[64 + j] + bhh[64 + j], bih[96 + j] + bhh[96 + j]);

    const float* xb = x + (size_t)b * Tn * 3;
    float* ob = g_h0 + (size_t)b * Tn * 64 + dir * 32 + j;

    // depth-2 x prefetch (x is L2-resident; 2 steps > 262-cyc L2 latency)
    float pfx[2][3];
#pragma unroll
    for (int s = 0; s < 2; s++) {
        const int te = dir ? (Tn - 1 - s) : s;
        pfx[s][0] = __ldg(xb + te*3 + 0);
        pfx[s][1] = __ldg(xb + te*3 + 1);
        pfx[s][2] = __ldg(xb + te*3 + 2);
    }

    float h = 0.0f, c = 0.0f;
    for (int t = 0; t < Tn; t++) {
        const int s = t & 1;
        unsigned long long xd0 = dup2(pfx[s][0]);
        unsigned long long xd1 = dup2(pfx[s][1]);
        unsigned long long xd2 = dup2(pfx[s][2]);

        const int tn = t + 2;
        if (tn < Tn) {
            const int te = dir ? (Tn - 1 - tn) : tn;
            pfx[s][0] = __ldg(xb + te*3 + 0);
            pfx[s][1] = __ldg(xb + te*3 + 1);
            pfx[s][2] = __ldg(xb + te*3 + 2);
        }

        unsigned long long accP = biasP, accQ = biasQ;
        ffma2(accP, wiP[0], xd0); ffma2(accQ, wiQ[0], xd0);
        ffma2(accP, wiP[1], xd1); ffma2(accQ, wiQ[1], xd1);
        ffma2(accP, wiP[2], xd2); ffma2(accQ, wiQ[2], xd2);

#pragma unroll
        for (int k = 0; k < 32; k++) {
            unsigned long long h2 = dup2(__shfl_sync(0xffffffffu, h, k));
            ffma2(accP, whP[k], h2);
            ffma2(accQ, whQ[k], h2);
        }

        float zi, zf, zg, zo;
        unpack2(accP, zi, zf);
        unpack2(accQ, zg, zo);
        const float ig = sigf(zi);
        const float fg = sigf(zf);
        const float gg = tanh_f(zg);
        const float og = sigf(zo);
        c = fg * c + ig * gg;
        h = og * tanh_f(c);

        const int te = dir ? (Tn - 1 - t) : t;
        ob[(size_t)te * 64] = h;
    }
}

// ---------------------------------------------------------------------------
// Layer-1 input projection GEMM. Block: 128 threads, tile 128 gates x 32 batch,
// 4 timesteps per block (weight tile amortized). Thread tile: 4 gates x 8 batch,
// batch-pair FFMA2 (h pairs natural from LDS.128, w duplicated via MOV).
// ---------------------------------------------------------------------------
__global__ void __launch_bounds__(128) gx1_gemm(
    const float* __restrict__ wih1_f, const float* __restrict__ bih1_f, const float* __restrict__ bhh1_f,
    const float* __restrict__ wih1_b, const float* __restrict__ bih1_b, const float* __restrict__ bhh1_b)
{
    const int t0  = blockIdx.x * 4;
    const int b0  = blockIdx.y * 32;
    const int dir = blockIdx.z;
    const float* w  = dir ? wih1_b : wih1_f;
    const float* bi = dir ? bih1_b : bih1_f;
    const float* bh = dir ? bhh1_b : bhh1_f;

    __shared__ __align__(16) float w_s[64 * 132];   // [k][g], stride 132 (16B rows, 4-way write conflicts)
    __shared__ __align__(16) float h_s[64 * 36];    // [k][b], stride 36 (16B rows)
    __shared__ float bias_s[128];

    const int tid = threadIdx.x;
    for (int i = tid; i < 128 * 64; i += 128) {
        const int k = i & 63, g = i >> 6;
        w_s[k * 132 + g] = w[g * 64 + k];            // coalesced read along k
    }
    bias_s[tid] = bi[tid] + bh[tid];

    const int gl = (tid & 31) * 4;   // 4 consecutive gates
    const int bq = tid >> 5;         // batch octet: rows bq*8 .. bq*8+7

    for (int it = 0; it < 4; it++) {
        const int t = t0 + it;
        __syncthreads();
        for (int i = tid; i < 32 * 64; i += 128) {
            const int k = i & 63, bb = i >> 6;
            h_s[k * 36 + bb] = g_h0[((size_t)(b0 + bb) * Tn + t) * 64 + k];  // coalesced along k
        }
        __syncthreads();

        unsigned long long acc[4][4];  // [gate][batch-pair]
#pragma unroll
        for (int g = 0; g < 4; g++) {
            unsigned long long bg = dup2(bias_s[gl + g]);
#pragma unroll
            for (int p = 0; p < 4; p++) acc[g][p] = bg;
        }

#pragma unroll 4
        for (int k = 0; k < 64; k++) {
            const float4 wv = *reinterpret_cast<const float4*>(&w_s[k * 132 + gl]);
            unsigned long long wd[4];
            wd[0] = dup2(wv.x); wd[1] = dup2(wv.y); wd[2] = dup2(wv.z); wd[3] = dup2(wv.w);
            const float4* hr = reinterpret_cast<const float4*>(&h_s[k * 36 + bq * 8]);
            const float4 q0 = hr[0], q1 = hr[1];
            unsigned long long hp[4];
            hp[0] = pack2(q0.x, q0.y); hp[1] = pack2(q0.z, q0.w);
            hp[2] = pack2(q1.x, q1.y); hp[3] = pack2(q1.z, q1.w);
#pragma unroll
            for (int g = 0; g < 4; g++)
#pragma unroll
                for (int p = 0; p < 4; p++) ffma2(acc[g][p], wd[g], hp[p]);
        }

        // store: per batch row, 4 consecutive gates -> one STG.128
        float* outb = g_gx1 + (((size_t)dir * Tn + t) * Bn + b0 + bq * 8) * 128 + gl;
#pragma unroll
        for (int p = 0; p < 4; p++) {
            float v0e, v0o, v1e, v1o, v2e, v2o, v3e, v3o;
            unpack2(acc[0][p], v0e, v0o);
            unpack2(acc[1][p], v1e, v1o);
            unpack2(acc[2][p], v2e, v2o);
            unpack2(acc[3][p], v3e, v3o);
            float4 lo = make_float4(v0e, v1e, v2e, v3e);
            float4 hi = make_float4(v0o, v1o, v2o, v3o);
            *reinterpret_cast<float4*>(outb + (size_t)(2 * p) * 128)     = lo;
            *reinterpret_cast<float4*>(outb + (size_t)(2 * p + 1) * 128) = hi;
        }
    }
}

// ---------------------------------------------------------------------------
// Layer-1 bidirectional LSTM + fused classifier.
// Block: 256 threads = 8 warps; warps 0-3 fwd / 4-7 bwd for batch rows b..b+3.
// gx prefetched 4 steps ahead (covers DRAM 577 cyc). Classifier epilogue on
// smem-resident hn: warp r computes row r, warp-shuffle reduce.
// ---------------------------------------------------------------------------
__global__ void __launch_bounds__(256, 1) lstm_layer1_cls(
    const float* __restrict__ whh_f, const float* __restrict__ whh_b,
    const float* __restrict__ wc1, const float* __restrict__ bc1,
    const float* __restrict__ wc2, const float* __restrict__ bc2,
    float* __restrict__ out)
{
    const int warp = threadIdx.x >> 5;
    const int j    = threadIdx.x & 31;
    const int dir  = warp >> 2;
    const int wq   = warp & 3;
    const int b    = blockIdx.x * 4 + wq;
    const float* whh = dir ? whh_b : whh_f;

    unsigned long long whP[32], whQ[32];
    {
        const float4* rI = reinterpret_cast<const float4*>(whh + (0   + j) * 32);
        const float4* rF = reinterpret_cast<const float4*>(whh + (32  + j) * 32);
        const float4* rG = reinterpret_cast<const float4*>(whh + (64  + j) * 32);
        const float4* rO = reinterpret_cast<const float4*>(whh + (96  + j) * 32);
#pragma unroll
        for (int v = 0; v < 8; v++) {
            float4 a = rI[v], c = rF[v];
            whP[4*v+0] = pack2(a.x, c.x); whP[4*v+1] = pack2(a.y, c.y);
            whP[4*v+2] = pack2(a.z, c.z); whP[4*v+3] = pack2(a.w, c.w);
        }
#pragma unroll
        for (int v = 0; v < 8; v++) {
            float4 a = rG[v], c = rO[v];
            whQ[4*v+0] = pack2(a.x, c.x); whQ[4*v+1] = pack2(a.y, c.y);
            whQ[4*v+2] = pack2(a.z, c.z); whQ[4*v+3] = pack2(a.w, c.w);
        }
    }

    const float* gxd = g_gx1 + (size_t)dir * Tn * Bn * 128 + (size_t)b * 128 + j;

    // depth-4 prefetch ring (gx streams from DRAM/L2)
    float pf[4][4];
#pragma unroll
    for (int s = 0; s < 4; s++) {
        const int te = dir ? (Tn - 1 - s) : s;
        const float* p = gxd + (size_t)te * Bn * 128;
#pragma unroll
        for (int q = 0; q < 4; q++) pf[s][q] = __ldg(p + q * 32);
    }

    float h = 0.0f, c = 0.0f;
    for (int t = 0; t < Tn; t++) {
        const int s = t & 3;
        unsigned long long accP = pack2(pf[s][0], pf[s][1]);
        unsigned long long accQ = pack2(pf[s][2], pf[s][3]);

        const int tn = t + 4;
        if (tn < Tn) {
            const int te = dir ? (Tn - 1 - tn) : tn;
            const float* p = gxd + (size_t)te * Bn * 128;
#pragma unroll
            for (int q = 0; q < 4; q++) pf[s][q] = __ldg(p + q * 32);
        }

#pragma unroll
        for (int k = 0; k < 32; k++) {
            unsigned long long h2 = dup2(__shfl_sync(0xffffffffu, h, k));
            ffma2(accP, whP[k], h2);
            ffma2(accQ, whQ[k], h2);
        }

        float zi, zf, zg, zo;
        unpack2(accP, zi, zf);
        unpack2(accQ, zg, zo);
        const float ig = sigf(zi);
        const float fg = sigf(zf);
        const float gg = tanh_f(zg);
        const float og = sigf(zo);
        c = fg * c + ig * gg;
        h = og * tanh_f(c);
    }

    __shared__ float hsm[4][64];
    hsm[wq][dir * 32 + j] = h;
    __syncthreads();

    // Classifier: warp r handles batch row r; lane m = neuron m of the 32-wide hidden.
    if (warp < 4) {
        const int m = j;
        const float4* wr = reinterpret_cast<const float4*>(wc1 + m * 64);
        float a = __ldg(bc1 + m);
#pragma unroll
        for (int v = 0; v < 16; v++) {
            float4 w4 = __ldg(wr + v);
            a += w4.x * hsm[warp][4*v+0] + w4.y * hsm[warp][4*v+1]
               + w4.z * hsm[warp][4*v+2] + w4.w * hsm[warp][4*v+3];
        }
        a = fmaxf(a, 0.0f);
        float p0 = a * __ldg(wc2 + m);
        float p1 = a * __ldg(wc2 + 32 + m);
#pragma unroll
        for (int off = 16; off > 0; off >>= 1) {
            p0 += __shfl_xor_sync(0xffffffffu, p0, off);
            p1 += __shfl_xor_sync(0xffffffffu, p1, off);
        }
        if (j == 0) {
            const int gb = blockIdx.x * 4 + warp;
            out[gb * 2 + 0] = p0 + __ldg(bc2 + 0);
            out[gb * 2 + 1] = p1 + __ldg(bc2 + 1);
        }
    }
}

// ---------------------------------------------------------------------------
extern "C" void kernel_launch(void* const* d_in, const int* in_sizes, int n_in,
                              void* d_out, int out_size)
{
    (void)in_sizes; (void)n_in; (void)out_size;
    const float* x     = (const float*)d_in[0];
    const float* wih0f = (const float*)d_in[1];
    const float* whh0f = (const float*)d_in[2];
    const float* bih0f = (const float*)d_in[3];
    const float* bhh0f = (const float*)d_in[4];
    const float* wih0b = (const float*)d_in[5];
    const float* whh0b = (const float*)d_in[6];
    const float* bih0b = (const float*)d_in[7];
    const float* bhh0b = (const float*)d_in[8];
    const float* wih1f = (const float*)d_in[9];
    const float* whh1f = (const float*)d_in[10];
    const float* bih1f = (const float*)d_in[11];
    const float* bhh1f = (const float*)d_in[12];
    const float* wih1b = (const float*)d_in[13];
    const float* whh1b = (const float*)d_in[14];
    const float* bih1b = (const float*)d_in[15];
    const float* bhh1b = (const float*)d_in[16];
    const float* wc1   = (const float*)d_in[17];
    const float* bc1   = (const float*)d_in[18];
    const float* wc2   = (const float*)d_in[19];
    const float* bc2   = (const float*)d_in[20];

    lstm_layer0<<<dim3(Bn / 4, 2), 128>>>(x, wih0f, whh0f, bih0f, bhh0f,
                                          wih0b, whh0b, bih0b, bhh0b);
    gx1_gemm<<<dim3(Tn / 4, Bn / 32, 2), 128>>>(wih1f, bih1f, bhh1f,
                                                wih1b, bih1b, bhh1b);
    lstm_layer1_cls<<<dim3(Bn / 4), 256>>>(whh1f, whh1b,
                                           wc1, bc1, wc2, bc2, (float*)d_out);
}

// round 8
// speedup vs baseline: 1.2833x; 1.1565x over previous
#include <cuda_runtime.h>

#define Tn 512
#define Bn 256
#define Hn 32

// Scratch (no cudaMalloc allowed): device globals.
__device__ float g_h0[(size_t)Bn * Tn * 64];          // [B][T][64]  layer-0 output (fwd|bwd)
__device__ float g_gx1[(size_t)2 * Tn * Bn * 128];    // [dir][t][B][128] layer-1 input projection

// ---- packed f32x2 helpers (Blackwell FFMA2 path, PTX-only) ----
__device__ __forceinline__ unsigned long long pack2(float a, float b) {
    unsigned long long r; asm("mov.b64 %0,{%1,%2};" : "=l"(r) : "f"(a), "f"(b)); return r;
}
__device__ __forceinline__ unsigned long long dup2(float a) {
    unsigned long long r; asm("mov.b64 %0,{%1,%1};" : "=l"(r) : "f"(a)); return r;
}
__device__ __forceinline__ void unpack2(unsigned long long v, float& lo, float& hi) {
    asm("mov.b64 {%0,%1},%2;" : "=f"(lo), "=f"(hi) : "l"(v));
}
__device__ __forceinline__ void ffma2(unsigned long long& acc, unsigned long long a,
                                      unsigned long long b) {
    asm("fma.rn.f32x2 %0,%1,%2,%0;" : "+l"(acc) : "l"(a), "l"(b));
}
__device__ __forceinline__ unsigned long long add2(unsigned long long a, unsigned long long b) {
    unsigned long long r; asm("add.rn.f32x2 %0,%1,%2;" : "=l"(r) : "l"(a), "l"(b)); return r;
}

// ---- fast-but-accurate activations (ex2/rcp approx, ~1e-7 class) ----
__device__ __forceinline__ float ex2f(float x) {
    float r; asm("ex2.approx.f32 %0,%1;" : "=f"(r) : "f"(x)); return r;
}
__device__ __forceinline__ float rcpf(float x) {
    float r; asm("rcp.approx.f32 %0,%1;" : "=f"(r) : "f"(x)); return r;
}
__device__ __forceinline__ float sigf(float x) {
    // 1/(1+2^(-x*log2e));  x->-inf: ex2->inf, rcp(inf)=0  (correct limit)
    return rcpf(1.0f + ex2f(-1.4426950408889634f * x));
}
__device__ __forceinline__ float tanh_f(float x) {
    // tanh(x) = 1 - 2/(2^(2x*log2e)+1);  handles +-inf correctly via ex2/rcp
    return fmaf(-2.0f, rcpf(1.0f + ex2f(2.8853900817779268f * x)), 1.0f);
}

// ---------------------------------------------------------------------------
// Layer-0 bidirectional LSTM. One warp = one (batch row, direction).
// h broadcast via smem (STS + syncwarp + 8x LDS.128 broadcast). FFMA2 paired
// over k (natural packing, zero dup MOVs), 2 split accumulators per gate.
// ---------------------------------------------------------------------------
__global__ void __launch_bounds__(128, 1) lstm_layer0(
    const float* __restrict__ x,
    const float* __restrict__ wih_f, const float* __restrict__ whh_f,
    const float* __restrict__ bih_f, const float* __restrict__ bhh_f,
    const float* __restrict__ wih_b, const float* __restrict__ whh_b,
    const float* __restrict__ bih_b, const float* __restrict__ bhh_b)
{
    const int dir  = blockIdx.y;
    const int warp = threadIdx.x >> 5;
    const int j    = threadIdx.x & 31;
    const int b    = blockIdx.x * 4 + warp;

    const float* wih = dir ? wih_b : wih_f;
    const float* whh = dir ? whh_b : whh_f;
    const float* bih = dir ? bih_b : bih_f;
    const float* bhh = dir ? bhh_b : bhh_f;

    // k-paired recurrent weights: wk[q][m] = (w[q*32+j][2m], w[q*32+j][2m+1])
    unsigned long long wk[4][16];
#pragma unroll
    for (int q = 0; q < 4; q++) {
        const ulonglong2* r = reinterpret_cast<const ulonglong2*>(whh + (q * 32 + j) * 32);
#pragma unroll
        for (int v = 0; v < 8; v++) {
            ulonglong2 u = r[v];
            wk[q][2*v]   = u.x;
            wk[q][2*v+1] = u.y;
        }
    }
    float wi[4][3], bias[4];
#pragma unroll
    for (int q = 0; q < 4; q++) {
        const int row = q * 32 + j;
        wi[q][0] = wih[row*3+0]; wi[q][1] = wih[row*3+1]; wi[q][2] = wih[row*3+2];
        bias[q]  = bih[row] + bhh[row];
    }

    __shared__ __align__(16) float hx[4][2][32];   // [warp][buf][j]

    const float* xb = x + (size_t)b * Tn * 3;
    float* ob = g_h0 + (size_t)b * Tn * 64 + dir * 32 + j;

    // depth-2 x prefetch
    float pfx[2][3];
#pragma unroll
    for (int s = 0; s < 2; s++) {
        const int te = dir ? (Tn - 1 - s) : s;
        pfx[s][0] = __ldg(xb + te*3 + 0);
        pfx[s][1] = __ldg(xb + te*3 + 1);
        pfx[s][2] = __ldg(xb + te*3 + 2);
    }

    float h = 0.0f, c = 0.0f;
    for (int t = 0; t < Tn; t++) {
        const int s = t & 1;

        // gate init: bias + W_ih * x_t   (off critical path: uses prefetched x)
        float zx[4];
#pragma unroll
        for (int q = 0; q < 4; q++)
            zx[q] = fmaf(wi[q][2], pfx[s][2],
                    fmaf(wi[q][1], pfx[s][1],
                    fmaf(wi[q][0], pfx[s][0], bias[q])));

        const int tn = t + 2;
        if (tn < Tn) {
            const int te = dir ? (Tn - 1 - tn) : tn;
            pfx[s][0] = __ldg(xb + te*3 + 0);
            pfx[s][1] = __ldg(xb + te*3 + 1);
            pfx[s][2] = __ldg(xb + te*3 + 2);
        }

        // broadcast h through smem
        hx[warp][s][j] = h;
        __syncwarp(0xffffffffu);
        const ulonglong2* hp = reinterpret_cast<const ulonglong2*>(&hx[warp][s][0]);

        unsigned long long a0[4], a1[4];
#pragma unroll
        for (int q = 0; q < 4; q++) { a0[q] = pack2(zx[q], 0.0f); a1[q] = 0ull; }

#pragma unroll
        for (int v = 0; v < 8; v++) {
            const ulonglong2 u = hp[v];            // k = 4v..4v+3 (two packed pairs)
#pragma unroll
            for (int q = 0; q < 4; q++) {
                ffma2(a0[q], wk[q][2*v],   u.x);
                ffma2(a1[q], wk[q][2*v+1], u.y);
            }
        }

        float z[4];
#pragma unroll
        for (int q = 0; q < 4; q++) {
            float lo, hi;
            unpack2(add2(a0[q], a1[q]), lo, hi);
            z[q] = lo + hi;
        }

        const float ig = sigf(z[0]);
        const float fg = sigf(z[1]);
        const float gg = tanh_f(z[2]);
        const float og = sigf(z[3]);
        c = fg * c + ig * gg;
        h = og * tanh_f(c);

        const int te = dir ? (Tn - 1 - t) : t;
        ob[(size_t)te * 64] = h;
    }
}

// ---------------------------------------------------------------------------
// Layer-1 input projection GEMM (unchanged from R6). Block: 128 threads,
// tile 128 gates x 32 batch, 4 timesteps per block.
// ---------------------------------------------------------------------------
__global__ void __launch_bounds__(128) gx1_gemm(
    const float* __restrict__ wih1_f, const float* __restrict__ bih1_f, const float* __restrict__ bhh1_f,
    const float* __restrict__ wih1_b, const float* __restrict__ bih1_b, const float* __restrict__ bhh1_b)
{
    const int t0  = blockIdx.x * 4;
    const int b0  = blockIdx.y * 32;
    const int dir = blockIdx.z;
    const float* w  = dir ? wih1_b : wih1_f;
    const float* bi = dir ? bih1_b : bih1_f;
    const float* bh = dir ? bhh1_b : bhh1_f;

    __shared__ __align__(16) float w_s[64 * 132];
    __shared__ __align__(16) float h_s[64 * 36];
    __shared__ float bias_s[128];

    const int tid = threadIdx.x;
    for (int i = tid; i < 128 * 64; i += 128) {
        const int k = i & 63, g = i >> 6;
        w_s[k * 132 + g] = w[g * 64 + k];
    }
    bias_s[tid] = bi[tid] + bh[tid];

    const int gl = (tid & 31) * 4;
    const int bq = tid >> 5;

    for (int it = 0; it < 4; it++) {
        const int t = t0 + it;
        __syncthreads();
        for (int i = tid; i < 32 * 64; i += 128) {
            const int k = i & 63, bb = i >> 6;
            h_s[k * 36 + bb] = g_h0[((size_t)(b0 + bb) * Tn + t) * 64 + k];
        }
        __syncthreads();

        unsigned long long acc[4][4];
#pragma unroll
        for (int g = 0; g < 4; g++) {
            unsigned long long bg = dup2(bias_s[gl + g]);
#pragma unroll
            for (int p = 0; p < 4; p++) acc[g][p] = bg;
        }

#pragma unroll 4
        for (int k = 0; k < 64; k++) {
            const float4 wv = *reinterpret_cast<const float4*>(&w_s[k * 132 + gl]);
            unsigned long long wd[4];
            wd[0] = dup2(wv.x); wd[1] = dup2(wv.y); wd[2] = dup2(wv.z); wd[3] = dup2(wv.w);
            const float4* hr = reinterpret_cast<const float4*>(&h_s[k * 36 + bq * 8]);
            const float4 q0 = hr[0], q1 = hr[1];
            unsigned long long hp[4];
            hp[0] = pack2(q0.x, q0.y); hp[1] = pack2(q0.z, q0.w);
            hp[2] = pack2(q1.x, q1.y); hp[3] = pack2(q1.z, q1.w);
#pragma unroll
            for (int g = 0; g < 4; g++)
#pragma unroll
                for (int p = 0; p < 4; p++) ffma2(acc[g][p], wd[g], hp[p]);
        }

        float* outb = g_gx1 + (((size_t)dir * Tn + t) * Bn + b0 + bq * 8) * 128 + gl;
#pragma unroll
        for (int p = 0; p < 4; p++) {
            float v0e, v0o, v1e, v1o, v2e, v2o, v3e, v3o;
            unpack2(acc[0][p], v0e, v0o);
            unpack2(acc[1][p], v1e, v1o);
            unpack2(acc[2][p], v2e, v2o);
            unpack2(acc[3][p], v3e, v3o);
            float4 lo = make_float4(v0e, v1e, v2e, v3e);
            float4 hi = make_float4(v0o, v1o, v2o, v3o);
            *reinterpret_cast<float4*>(outb + (size_t)(2 * p) * 128)     = lo;
            *reinterpret_cast<float4*>(outb + (size_t)(2 * p + 1) * 128) = hi;
        }
    }
}

// ---------------------------------------------------------------------------
// Layer-1 bidirectional LSTM + fused classifier. Same smem-broadcast /
// k-paired structure. Block: 256 threads; warps 0-3 fwd, 4-7 bwd, rows b..b+3.
// ---------------------------------------------------------------------------
__global__ void __launch_bounds__(256, 1) lstm_layer1_cls(
    const float* __restrict__ whh_f, const float* __restrict__ whh_b,
    const float* __restrict__ wc1, const float* __restrict__ bc1,
    const float* __restrict__ wc2, const float* __restrict__ bc2,
    float* __restrict__ out)
{
    const int warp = threadIdx.x >> 5;
    const int j    = threadIdx.x & 31;
    const int dir  = warp >> 2;
    const int wq   = warp & 3;
    const int b    = blockIdx.x * 4 + wq;
    const float* whh = dir ? whh_b : whh_f;

    unsigned long long wk[4][16];
#pragma unroll
    for (int q = 0; q < 4; q++) {
        const ulonglong2* r = reinterpret_cast<const ulonglong2*>(whh + (q * 32 + j) * 32);
#pragma unroll
        for (int v = 0; v < 8; v++) {
            ulonglong2 u = r[v];
            wk[q][2*v]   = u.x;
            wk[q][2*v+1] = u.y;
        }
    }

    __shared__ __align__(16) float hx[8][2][32];

    const float* gxd = g_gx1 + (size_t)dir * Tn * Bn * 128 + (size_t)b * 128 + j;

    // depth-4 gx prefetch ring (gx streams from DRAM/L2)
    float pf[4][4];
#pragma unroll
    for (int s = 0; s < 4; s++) {
        const int te = dir ? (Tn - 1 - s) : s;
        const float* p = gxd + (size_t)te * Bn * 128;
#pragma unroll
        for (int q = 0; q < 4; q++) pf[s][q] = __ldg(p + q * 32);
    }

    float h = 0.0f, c = 0.0f;
    for (int t = 0; t < Tn; t++) {
        const int s = t & 3;
        float zx[4];
#pragma unroll
        for (int q = 0; q < 4; q++) zx[q] = pf[s][q];

        const int tn = t + 4;
        if (tn < Tn) {
            const int te = dir ? (Tn - 1 - tn) : tn;
            const float* p = gxd + (size_t)te * Bn * 128;
#pragma unroll
            for (int q = 0; q < 4; q++) pf[s][q] = __ldg(p + q * 32);
        }

        const int sb = t & 1;
        hx[warp][sb][j] = h;
        __syncwarp(0xffffffffu);
        const ulonglong2* hp = reinterpret_cast<const ulonglong2*>(&hx[warp][sb][0]);

        unsigned long long a0[4], a1[4];
#pragma unroll
        for (int q = 0; q < 4; q++) { a0[q] = pack2(zx[q], 0.0f); a1[q] = 0ull; }

#pragma unroll
        for (int v = 0; v < 8; v++) {
            const ulonglong2 u = hp[v];
#pragma unroll
            for (int q = 0; q < 4; q++) {
                ffma2(a0[q], wk[q][2*v],   u.x);
                ffma2(a1[q], wk[q][2*v+1], u.y);
            }
        }

        float z[4];
#pragma unroll
        for (int q = 0; q < 4; q++) {
            float lo, hi;
            unpack2(add2(a0[q], a1[q]), lo, hi);
            z[q] = lo + hi;
        }

        const float ig = sigf(z[0]);
        const float fg = sigf(z[1]);
        const float gg = tanh_f(z[2]);
        const float og = sigf(z[3]);
        c = fg * c + ig * gg;
        h = og * tanh_f(c);
    }

    __shared__ float hsm[4][64];
    hsm[wq][dir * 32 + j] = h;
    __syncthreads();

    // Classifier: warp r handles batch row r; lane m = hidden neuron m.
    if (warp < 4) {
        const int m = j;
        const float4* wr = reinterpret_cast<const float4*>(wc1 + m * 64);
        float a = __ldg(bc1 + m);
#pragma unroll
        for (int v = 0; v < 16; v++) {
            float4 w4 = __ldg(wr + v);
            a += w4.x * hsm[warp][4*v+0] + w4.y * hsm[warp][4*v+1]
               + w4.z * hsm[warp][4*v+2] + w4.w * hsm[warp][4*v+3];
        }
        a = fmaxf(a, 0.0f);
        float p0 = a * __ldg(wc2 + m);
        float p1 = a * __ldg(wc2 + 32 + m);
#pragma unroll
        for (int off = 16; off > 0; off >>= 1) {
            p0 += __shfl_xor_sync(0xffffffffu, p0, off);
            p1 += __shfl_xor_sync(0xffffffffu, p1, off);
        }
        if (j == 0) {
            const int gb = blockIdx.x * 4 + warp;
            out[gb * 2 + 0] = p0 + __ldg(bc2 + 0);
            out[gb * 2 + 1] = p1 + __ldg(bc2 + 1);
        }
    }
}

// ---------------------------------------------------------------------------
extern "C" void kernel_launch(void* const* d_in, const int* in_sizes, int n_in,
                              void* d_out, int out_size)
{
    (void)in_sizes; (void)n_in; (void)out_size;
    const float* x     = (const float*)d_in[0];
    const float* wih0f = (const float*)d_in[1];
    const float* whh0f = (const float*)d_in[2];
    const float* bih0f = (const float*)d_in[3];
    const float* bhh0f = (const float*)d_in[4];
    const float* wih0b = (const float*)d_in[5];
    const float* whh0b = (const float*)d_in[6];
    const float* bih0b = (const float*)d_in[7];
    const float* bhh0b = (const float*)d_in[8];
    const float* wih1f = (const float*)d_in[9];
    const float* whh1f = (const float*)d_in[10];
    const float* bih1f = (const float*)d_in[11];
    const float* bhh1f = (const float*)d_in[12];
    const float* wih1b = (const float*)d_in[13];
    const float* whh1b = (const float*)d_in[14];
    const float* bih1b = (const float*)d_in[15];
    const float* bhh1b = (const float*)d_in[16];
    const float* wc1   = (const float*)d_in[17];
    const float* bc1   = (const float*)d_in[18];
    const float* wc2   = (const float*)d_in[19];
    const float* bc2   = (const float*)d_in[20];

    lstm_layer0<<<dim3(Bn / 4, 2), 128>>>(x, wih0f, whh0f, bih0f, bhh0f,
                                          wih0b, whh0b, bih0b, bhh0b);
    gx1_gemm<<<dim3(Tn / 4, Bn / 32, 2), 128>>>(wih1f, bih1f, bhh1f,
                                                wih1b, bih1b, bhh1b);
    lstm_layer1_cls<<<dim3(Bn / 4), 256>>>(whh1f, whh1b,
                                           wc1, bc1, wc2, bc2, (float*)d_out);
}

// round 9
// speedup vs baseline: 1.7078x; 1.3308x over previous
#include <cuda_runtime.h>

#define Tn 512
#define Bn 256
#define Hn 32

// Scratch (no cudaMalloc allowed): device globals.
__device__ float g_h0[(size_t)Bn * Tn * 64];          // [B][T][64]  layer-0 output (fwd|bwd)
__device__ float g_gx1[(size_t)2 * Tn * Bn * 128];    // [dir][t][B][128] layer-1 input proj (gate-scaled)
__device__ float g_hn[Bn * 64];                       // [B][64] final hidden (fwd|bwd)

// Activation scaling constants (folded into weights):
//   sig(z)  = rcp(1 + ex2(S*z)),          S = -log2(e)
//   tanh(z) = 1 - 2*rcp(1 + ex2(K*z)),    K = 2*log2(e)
#define SCONST (-1.4426950408889634f)
#define KCONST ( 2.8853900817779268f)

// ---- packed f32x2 helpers ----
__device__ __forceinline__ unsigned long long pack2(float a, float b) {
    unsigned long long r; asm("mov.b64 %0,{%1,%2};" : "=l"(r) : "f"(a), "f"(b)); return r;
}
__device__ __forceinline__ unsigned long long dup2(float a) {
    unsigned long long r; asm("mov.b64 %0,{%1,%1};" : "=l"(r) : "f"(a)); return r;
}
__device__ __forceinline__ void unpack2(unsigned long long v, float& lo, float& hi) {
    asm("mov.b64 {%0,%1},%2;" : "=f"(lo), "=f"(hi) : "l"(v));
}
__device__ __forceinline__ void ffma2(unsigned long long& acc, unsigned long long a,
                                      unsigned long long b) {
    asm("fma.rn.f32x2 %0,%1,%2,%0;" : "+l"(acc) : "l"(a), "l"(b));
}
__device__ __forceinline__ unsigned long long add2(unsigned long long a, unsigned long long b) {
    unsigned long long r; asm("add.rn.f32x2 %0,%1,%2;" : "=l"(r) : "l"(a), "l"(b)); return r;
}

__device__ __forceinline__ float ex2f(float x) {
    float r; asm("ex2.approx.f32 %0,%1;" : "=f"(r) : "f"(x)); return r;
}
__device__ __forceinline__ float rcpf(float x) {
    float r; asm("rcp.approx.f32 %0,%1;" : "=f"(r) : "f"(x)); return r;
}
// inputs already pre-scaled:
__device__ __forceinline__ float sig_pre(float zs) {   // zs = S*z
    return rcpf(1.0f + ex2f(zs));
}
__device__ __forceinline__ float tanh_pre(float zk) {  // zk = K*z
    return fmaf(-2.0f, rcpf(1.0f + ex2f(zk)), 1.0f);
}

// h-exchange through smem without WARPSYNC: STS then LDS from the same
// converged warp are processed in-order by the LSU; asm volatile pins the
// compiler ordering.
__device__ __forceinline__ void sts_f32(unsigned addr, float v) {
    asm volatile("st.shared.f32 [%0], %1;" :: "r"(addr), "f"(v));
}
__device__ __forceinline__ void lds_v2u64(unsigned addr, unsigned long long& a,
                                          unsigned long long& b) {
    asm volatile("ld.shared.v2.u64 {%0,%1},[%2];" : "=l"(a), "=l"(b) : "r"(addr));
}

// ---------------------------------------------------------------------------
// Layer-0 bidirectional LSTM. One warp = one (batch row, direction).
// Gate rows pre-scaled (i,f,o by S; g by K). Cell state kept as C = K*c.
// ---------------------------------------------------------------------------
__global__ void __launch_bounds__(128, 1) lstm_layer0(
    const float* __restrict__ x,
    const float* __restrict__ wih_f, const float* __restrict__ whh_f,
    const float* __restrict__ bih_f, const float* __restrict__ bhh_f,
    const float* __restrict__ wih_b, const float* __restrict__ whh_b,
    const float* __restrict__ bih_b, const float* __restrict__ bhh_b)
{
    const int dir  = blockIdx.y;
    const int warp = threadIdx.x >> 5;
    const int j    = threadIdx.x & 31;
    const int b    = blockIdx.x * 4 + warp;

    const float* wih = dir ? wih_b : wih_f;
    const float* whh = dir ? whh_b : whh_f;
    const float* bih = dir ? bih_b : bih_f;
    const float* bhh = dir ? bhh_b : bhh_f;

    const float sc[4] = {SCONST, SCONST, KCONST, SCONST};

    // k-paired recurrent weights, pre-scaled per gate row.
    unsigned long long wk[4][16];
#pragma unroll
    for (int q = 0; q < 4; q++) {
        const float4* r = reinterpret_cast<const float4*>(whh + (q * 32 + j) * 32);
        const float s = sc[q];
#pragma unroll
        for (int v = 0; v < 8; v++) {
            float4 f = r[v];
            wk[q][2*v]   = pack2(f.x * s, f.y * s);
            wk[q][2*v+1] = pack2(f.z * s, f.w * s);
        }
    }
    float wi[4][3], bias[4];
#pragma unroll
    for (int q = 0; q < 4; q++) {
        const int row = q * 32 + j;
        const float s = sc[q];
        wi[q][0] = wih[row*3+0] * s;
        wi[q][1] = wih[row*3+1] * s;
        wi[q][2] = wih[row*3+2] * s;
        bias[q]  = (bih[row] + bhh[row]) * s;
    }

    __shared__ __align__(16) float hx[4][32];
    const unsigned st_addr = (unsigned)__cvta_generic_to_shared(&hx[warp][j]);
    const unsigned ld_base = (unsigned)__cvta_generic_to_shared(&hx[warp][0]);

    // x prefetch (depth 2), pointer-stepped
    const float* xb = x + (size_t)b * Tn * 3;
    const int xstep = dir ? -3 : 3;
    const float* xpf = dir ? (xb + (Tn - 1) * 3) : xb;
    float pfx[2][3];
#pragma unroll
    for (int s = 0; s < 2; s++) {
        pfx[s][0] = __ldg(xpf + 0);
        pfx[s][1] = __ldg(xpf + 1);
        pfx[s][2] = __ldg(xpf + 2);
        xpf += xstep;
    }

    float* obp = g_h0 + (size_t)b * Tn * 64 + dir * 32 + j
               + (dir ? (size_t)(Tn - 1) * 64 : 0);
    const int ostep = dir ? -64 : 64;

    float h = 0.0f, C = 0.0f;   // C = K * c
    for (int t = 0; t < Tn; t++) {
        const int s = t & 1;

        // pre-scaled gate init (off critical path)
        float zx[4];
#pragma unroll
        for (int q = 0; q < 4; q++)
            zx[q] = fmaf(wi[q][2], pfx[s][2],
                    fmaf(wi[q][1], pfx[s][1],
                    fmaf(wi[q][0], pfx[s][0], bias[q])));

        if (t + 2 < Tn) {
            pfx[s][0] = __ldg(xpf + 0);
            pfx[s][1] = __ldg(xpf + 1);
            pfx[s][2] = __ldg(xpf + 2);
            xpf += xstep;
        }

        // h broadcast (in-order LSU: no warpsync)
        sts_f32(st_addr, h);

        unsigned long long a0[4], a1[4];
#pragma unroll
        for (int q = 0; q < 4; q++) { a0[q] = pack2(zx[q], 0.0f); a1[q] = 0ull; }

#pragma unroll
        for (int v = 0; v < 8; v++) {
            unsigned long long ux, uy;
            lds_v2u64(ld_base + 16u * v, ux, uy);
#pragma unroll
            for (int q = 0; q < 4; q++) {
                ffma2(a0[q], wk[q][2*v],   ux);
                ffma2(a1[q], wk[q][2*v+1], uy);
            }
        }

        float z[4];
#pragma unroll
        for (int q = 0; q < 4; q++) {
            float lo, hi;
            unpack2(add2(a0[q], a1[q]), lo, hi);
            z[q] = lo + hi;
        }

        const float ig  = sig_pre(z[0]);
        const float fg  = sig_pre(z[1]);
        // gg' = K * tanh(zg):  fma(-2K, rcp, K)
        const float ggK = fmaf(-2.0f * KCONST, rcpf(1.0f + ex2f(z[2])), KCONST);
        const float og  = sig_pre(z[3]);

        C = fmaf(fg, C, ig * ggK);                 // C = K*c
        const float th = tanh_pre(C);              // tanh(c)
        h = og * th;

        *obp = h;
        obp += ostep;
    }
}

// ---------------------------------------------------------------------------
// Layer-1 input projection GEMM; output pre-scaled per gate row (so layer-1's
// activations consume it directly). Tile 128 gates x 32 batch, 4 timesteps.
// ---------------------------------------------------------------------------
__global__ void __launch_bounds__(128) gx1_gemm(
    const float* __restrict__ wih1_f, const float* __restrict__ bih1_f, const float* __restrict__ bhh1_f,
    const float* __restrict__ wih1_b, const float* __restrict__ bih1_b, const float* __restrict__ bhh1_b)
{
    const int t0  = blockIdx.x * 4;
    const int b0  = blockIdx.y * 32;
    const int dir = blockIdx.z;
    const float* w  = dir ? wih1_b : wih1_f;
    const float* bi = dir ? bih1_b : bih1_f;
    const float* bh = dir ? bhh1_b : bhh1_f;

    __shared__ __align__(16) float w_s[64 * 132];
    __shared__ __align__(16) float h_s[64 * 36];
    __shared__ float bias_s[128];

    const int tid = threadIdx.x;
    for (int i = tid; i < 128 * 64; i += 128) {
        const int k = i & 63, g = i >> 6;
        const float s = ((g >> 5) == 2) ? KCONST : SCONST;
        w_s[k * 132 + g] = w[g * 64 + k] * s;
    }
    {
        const float s = ((tid >> 5) == 2) ? KCONST : SCONST;
        bias_s[tid] = (bi[tid] + bh[tid]) * s;
    }

    const int gl = (tid & 31) * 4;
    const int bq = tid >> 5;

    for (int it = 0; it < 4; it++) {
        const int t = t0 + it;
        __syncthreads();
        for (int i = tid; i < 32 * 64; i += 128) {
            const int k = i & 63, bb = i >> 6;
            h_s[k * 36 + bb] = g_h0[((size_t)(b0 + bb) * Tn + t) * 64 + k];
        }
        __syncthreads();

        unsigned long long acc[4][4];
#pragma unroll
        for (int g = 0; g < 4; g++) {
            unsigned long long bg = dup2(bias_s[gl + g]);
#pragma unroll
            for (int p = 0; p < 4; p++) acc[g][p] = bg;
        }

#pragma unroll 4
        for (int k = 0; k < 64; k++) {
            const float4 wv = *reinterpret_cast<const float4*>(&w_s[k * 132 + gl]);
            unsigned long long wd[4];
            wd[0] = dup2(wv.x); wd[1] = dup2(wv.y); wd[2] = dup2(wv.z); wd[3] = dup2(wv.w);
            const float4* hr = reinterpret_cast<const float4*>(&h_s[k * 36 + bq * 8]);
            const float4 q0 = hr[0], q1 = hr[1];
            unsigned long long hp[4];
            hp[0] = pack2(q0.x, q0.y); hp[1] = pack2(q0.z, q0.w);
            hp[2] = pack2(q1.x, q1.y); hp[3] = pack2(q1.z, q1.w);
#pragma unroll
            for (int g = 0; g < 4; g++)
#pragma unroll
                for (int p = 0; p < 4; p++) ffma2(acc[g][p], wd[g], hp[p]);
        }

        float* outb = g_gx1 + (((size_t)dir * Tn + t) * Bn + b0 + bq * 8) * 128 + gl;
#pragma unroll
        for (int p = 0; p < 4; p++) {
            float v0e, v0o, v1e, v1o, v2e, v2o, v3e, v3o;
            unpack2(acc[0][p], v0e, v0o);
            unpack2(acc[1][p], v1e, v1o);
            unpack2(acc[2][p], v2e, v2o);
            unpack2(acc[3][p], v3e, v3o);
            float4 lo = make_float4(v0e, v1e, v2e, v3e);
            float4 hi = make_float4(v0o, v1o, v2o, v3o);
            *reinterpret_cast<float4*>(outb + (size_t)(2 * p) * 128)     = lo;
            *reinterpret_cast<float4*>(outb + (size_t)(2 * p + 1) * 128) = hi;
        }
    }
}

// ---------------------------------------------------------------------------
// Layer-1 bidirectional LSTM (grid (B/4, 2), 128 threads: 4 chains/SM,
// 128-cyc FFMA floor like layer0). gx (pre-scaled) prefetched 4 deep.
// ---------------------------------------------------------------------------
__global__ void __launch_bounds__(128, 1) lstm_layer1(
    const float* __restrict__ whh_f, const float* __restrict__ whh_b)
{
    const int dir  = blockIdx.y;
    const int warp = threadIdx.x >> 5;
    const int j    = threadIdx.x & 31;
    const int b    = blockIdx.x * 4 + warp;
    const float* whh = dir ? whh_b : whh_f;

    const float sc[4] = {SCONST, SCONST, KCONST, SCONST};
    unsigned long long wk[4][16];
#pragma unroll
    for (int q = 0; q < 4; q++) {
        const float4* r = reinterpret_cast<const float4*>(whh + (q * 32 + j) * 32);
        const float s = sc[q];
#pragma unroll
        for (int v = 0; v < 8; v++) {
            float4 f = r[v];
            wk[q][2*v]   = pack2(f.x * s, f.y * s);
            wk[q][2*v+1] = pack2(f.z * s, f.w * s);
        }
    }

    __shared__ __align__(16) float hx[4][32];
    const unsigned st_addr = (unsigned)__cvta_generic_to_shared(&hx[warp][j]);
    const unsigned ld_base = (unsigned)__cvta_generic_to_shared(&hx[warp][0]);

    const long long gstep = dir ? -(long long)Bn * 128 : (long long)Bn * 128;
    const float* gpf = g_gx1 + (size_t)dir * Tn * Bn * 128 + (size_t)b * 128 + j
                     + (dir ? (size_t)(Tn - 1) * Bn * 128 : 0);

    float pf[4][4];
#pragma unroll
    for (int s = 0; s < 4; s++) {
#pragma unroll
        for (int q = 0; q < 4; q++) pf[s][q] = __ldg(gpf + q * 32);
        gpf += gstep;
    }

    float h = 0.0f, C = 0.0f;
    for (int t = 0; t < Tn; t++) {
        const int s = t & 3;
        float zx[4];
#pragma unroll
        for (int q = 0; q < 4; q++) zx[q] = pf[s][q];

        if (t + 4 < Tn) {
#pragma unroll
            for (int q = 0; q < 4; q++) pf[s][q] = __ldg(gpf + q * 32);
            gpf += gstep;
        }

        sts_f32(st_addr, h);

        unsigned long long a0[4], a1[4];
#pragma unroll
        for (int q = 0; q < 4; q++) { a0[q] = pack2(zx[q], 0.0f); a1[q] = 0ull; }

#pragma unroll
        for (int v = 0; v < 8; v++) {
            unsigned long long ux, uy;
            lds_v2u64(ld_base + 16u * v, ux, uy);
#pragma unroll
            for (int q = 0; q < 4; q++) {
                ffma2(a0[q], wk[q][2*v],   ux);
                ffma2(a1[q], wk[q][2*v+1], uy);
            }
        }

        float z[4];
#pragma unroll
        for (int q = 0; q < 4; q++) {
            float lo, hi;
            unpack2(add2(a0[q], a1[q]), lo, hi);
            z[q] = lo + hi;
        }

        const float ig  = sig_pre(z[0]);
        const float fg  = sig_pre(z[1]);
        const float ggK = fmaf(-2.0f * KCONST, rcpf(1.0f + ex2f(z[2])), KCONST);
        const float og  = sig_pre(z[3]);

        C = fmaf(fg, C, ig * ggK);
        h = og * tanh_pre(C);
    }

    g_hn[b * 64 + dir * 32 + j] = h;
}

// ---------------------------------------------------------------------------
// Classifier: out = relu(hn @ wc1^T + bc1) @ wc2^T + bc2.
// One warp per batch row; lane m = hidden neuron m; shuffle reduce.
// ---------------------------------------------------------------------------
__global__ void __launch_bounds__(256) classifier(
    const float* __restrict__ wc1, const float* __restrict__ bc1,
    const float* __restrict__ wc2, const float* __restrict__ bc2,
    float* __restrict__ out)
{
    const int warp = threadIdx.x >> 5;
    const int j    = threadIdx.x & 31;
    const int row  = blockIdx.x * 8 + warp;

    const float4* wr = reinterpret_cast<const float4*>(wc1 + j * 64);
    const float4* hr = reinterpret_cast<const float4*>(g_hn + row * 64);

    float a = __ldg(bc1 + j);
#pragma unroll
    for (int v = 0; v < 16; v++) {
        float4 w4 = __ldg(wr + v);
        float4 h4 = __ldg(hr + v);
        a += w4.x * h4.x + w4.y * h4.y + w4.z * h4.z + w4.w * h4.w;
    }
    a = fmaxf(a, 0.0f);
    float p0 = a * __ldg(wc2 + j);
    float p1 = a * __ldg(wc2 + 32 + j);
#pragma unroll
    for (int off = 16; off > 0; off >>= 1) {
        p0 += __shfl_xor_sync(0xffffffffu, p0, off);
        p1 += __shfl_xor_sync(0xffffffffu, p1, off);
    }
    if (j == 0) {
        out[row * 2 + 0] = p0 + __ldg(bc2 + 0);
        out[row * 2 + 1] = p1 + __ldg(bc2 + 1);
    }
}

// ---------------------------------------------------------------------------
extern "C" void kernel_launch(void* const* d_in, const int* in_sizes, int n_in,
                              void* d_out, int out_size)
{
    (void)in_sizes; (void)n_in; (void)out_size;
    const float* x     = (const float*)d_in[0];
    const float* wih0f = (const float*)d_in[1];
    const float* whh0f = (const float*)d_in[2];
    const float* bih0f = (const float*)d_in[3];
    const float* bhh0f = (const float*)d_in[4];
    const float* wih0b = (const float*)d_in[5];
    const float* whh0b = (const float*)d_in[6];
    const float* bih0b = (const float*)d_in[7];
    const float* bhh0b = (const float*)d_in[8];
    const float* wih1f = (const float*)d_in[9];
    const float* whh1f = (const float*)d_in[10];
    const float* bih1f = (const float*)d_in[11];
    const float* bhh1f = (const float*)d_in[12];
    const float* wih1b = (const float*)d_in[13];
    const float* whh1b = (const float*)d_in[14];
    const float* bih1b = (const float*)d_in[15];
    const float* bhh1b = (const float*)d_in[16];
    const float* wc1   = (const float*)d_in[17];
    const float* bc1   = (const float*)d_in[18];
    const float* wc2   = (const float*)d_in[19];
    const float* bc2   = (const float*)d_in[20];

    lstm_layer0<<<dim3(Bn / 4, 2), 128>>>(x, wih0f, whh0f, bih0f, bhh0f,
                                          wih0b, whh0b, bih0b, bhh0b);
    gx1_gemm<<<dim3(Tn / 4, Bn / 32, 2), 128>>>(wih1f, bih1f, bhh1f,
                                                wih1b, bih1b, bhh1b);
    lstm_layer1<<<dim3(Bn / 4, 2), 128>>>(whh1f, whh1b);
    classifier<<<dim3(Bn / 8), 256>>>(wc1, bc1, wc2, bc2, (float*)d_out);
}